// round 17
// baseline (speedup 1.0000x reference)
#include <cuda_runtime.h>
#include <math.h>
#include <stdint.h>

#define BB 128
#define TT 512
#define HH 1024
#define NCTA 128
#define NTHR 544
#define NSTG 3

// smem: stage s<3 (49152B): A 32KB @ s*49152 ([mb4][pair32][row32] uint2), B 16KB @ +32768
//       Zs float[128][72] @147456; sb @184320; mbars @184832
#define STAGE_SZ 49152
#define ZS_OFF   147456
#define SB_OFF   184320
#define MB_OFF   184832
#define EMPTY_MB(s)  (MB_OFF + (s) * 48)
#define B_MB(s)      (MB_OFF + (s) * 48 + 8)
#define A_MB(s, mb)  (MB_OFF + (s) * 48 + 16 + (mb) * 8)
#define SMEM_DYN 185088

// ---- persistent device state: packed (bf16-hi, bf16-lo) pairs ----
// A images: [t/parity][m-block][pair][row32], row stored at (m&31)^((p&3)<<2)
// B images: [kh][ch][cb64][pair32][col64], col stored at c^((p&3)<<2)
__device__ __align__(16) uint2 g_x [TT][4][128][32];
__device__ __align__(16) uint2 g_h0[2][4][512][32];
__device__ __align__(16) uint2 g_h1[2][4][512][32];
__device__ __align__(16) uint2 g_w0[2][10][64][32][64];
__device__ __align__(16) uint2 g_w1[2][16][64][32][64];
__device__ float g_zx[2][2][64][128][64];   // [t-par][layer][pair][row][col] partial Z
__device__ unsigned g_zcnt[64];             // per-pair exchange counter
__device__ int g_perm[BB];
__device__ int g_plen[BB];
__device__ int g_nt[TT];
__device__ unsigned g_cntA, g_genA, g_cntB, g_genB;

__device__ __forceinline__ float sigf(float x) {
    return __fdividef(1.0f, 1.0f + __expf(-x));
}
__device__ __forceinline__ float tanf_fast(float x) {
    float cx = fminf(fmaxf(x, -15.0f), 15.0f);
    float e = __expf(2.0f * cx);
    return (e - 1.0f) * __fdividef(1.0f, e + 1.0f);
}
__device__ __forceinline__ uint32_t s2u(const void* p) {
    uint32_t a;
    asm("{ .reg .u64 t; cvta.to.shared.u64 t, %1; cvt.u32.u64 %0, t; }" : "=r"(a) : "l"(p));
    return a;
}
__device__ __forceinline__ uint2 pack_pair(float e0, float e1) {
    uint32_t hi, lo;
    asm("cvt.rn.bf16x2.f32 %0, %1, %2;" : "=r"(hi) : "f"(e1), "f"(e0));
    float r0 = e0 - __uint_as_float(hi << 16);
    float r1 = e1 - __uint_as_float(hi & 0xFFFF0000u);
    asm("cvt.rn.bf16x2.f32 %0, %1, %2;" : "=r"(lo) : "f"(r1), "f"(r0));
    return make_uint2(hi, lo);
}
__device__ __forceinline__ void bmma(float* c, uint32_t a0, uint32_t a1, uint32_t a2,
                                     uint32_t a3, uint32_t b0, uint32_t b1) {
    asm("mma.sync.aligned.m16n8k16.row.col.f32.bf16.bf16.f32 "
        "{%0,%1,%2,%3},{%4,%5,%6,%7},{%8,%9},{%0,%1,%2,%3};"
        : "+f"(c[0]), "+f"(c[1]), "+f"(c[2]), "+f"(c[3])
        : "r"(a0), "r"(a1), "r"(a2), "r"(a3), "r"(b0), "r"(b1));
}
__device__ __forceinline__ void mbar_init(uint32_t b, uint32_t n) {
    asm volatile("mbarrier.init.shared.b64 [%0], %1;" :: "r"(b), "r"(n) : "memory");
}
__device__ __forceinline__ void mexpect(uint32_t b, uint32_t tx) {
    asm volatile("mbarrier.arrive.expect_tx.shared.b64 _, [%0], %1;" :: "r"(b), "r"(tx) : "memory");
}
__device__ __forceinline__ void marrive(uint32_t b) {
    asm volatile("mbarrier.arrive.shared.b64 _, [%0];" :: "r"(b) : "memory");
}
__device__ __forceinline__ void mwait(uint32_t b, uint32_t ph) {
    asm volatile(
        "{\n\t.reg .pred P;\n"
        "W_%=:\n\t"
        "mbarrier.try_wait.parity.acquire.cta.shared::cta.b64 P, [%0], %1, 0x989680;\n\t"
        "@P bra D_%=;\n\t"
        "bra W_%=;\n"
        "D_%=:\n\t}"
        :: "r"(b), "r"(ph) : "memory");
}
__device__ __forceinline__ void bulk(uint32_t dst, const void* src, uint32_t bytes, uint32_t mbar) {
    asm volatile("cp.async.bulk.shared::cluster.global.mbarrier::complete_tx::bytes [%0], [%1], %2, [%3];"
        :: "r"(dst), "l"(src), "r"(bytes), "r"(mbar) : "memory");
}
__device__ __forceinline__ void barc() {   // compute-warps barrier (512 thr)
    asm volatile("bar.sync 1, 512;" ::: "memory");
}
__device__ __forceinline__ void arrive_evt(unsigned* cnt, unsigned* gen) {
    __threadfence();
    if (atomicAdd(cnt, 1u) == NCTA - 1) {
        *cnt = 0;
        __threadfence();
        atomicAdd(gen, 1u);
    }
}
__device__ __forceinline__ void wait_gen(volatile unsigned* gen, unsigned base, unsigned want) {
    while (*gen - base < want) { __nanosleep(64); }
    __threadfence();
}

// ---- prep: sort rows by length (desc), alive counts ----
__global__ void prep_perm(const int* __restrict__ il) {
    __shared__ int sl[BB];
    int i = threadIdx.x;
    sl[i] = il[i];
    __syncthreads();
    int L = sl[i], r = 0;
    for (int j = 0; j < BB; j++) {
        int Lj = sl[j];
        if (Lj > L || (Lj == L && j < i)) r++;
    }
    g_perm[r] = i;
    g_plen[r] = L;
    for (int k = 0; k < 4; k++) {
        int t = i * 4 + k;
        int c = 0;
        for (int j = 0; j < BB; j++) c += (sl[j] > t);
        g_nt[t] = c;
    }
}

// ---- prep: embeddings -> g_x (permuted rows, block layout, A-swizzled) ----
__global__ void prep_x(const int* __restrict__ ib, const float* __restrict__ emb) {
    const int N = TT * 128 * BB;
    for (int i = blockIdx.x * blockDim.x + threadIdx.x; i < N;
         i += gridDim.x * blockDim.x) {
        int m = i & 127;
        int p = (i >> 7) & 127;
        int t = i >> 14;
        const float* s = emb + (size_t)ib[g_perm[m] * TT + t] * 256 + 2 * p;
        g_x[t][m >> 5][p][(m & 31) ^ ((p & 3) << 2)] = pack_pair(s[0], s[1]);
    }
}

// ---- prep: W -> packed [kh][ch][cb64][pair32][col64'] (B-swizzled) ----
__global__ void prep_w(const float* __restrict__ W0, const float* __restrict__ W1) {
    const long n0 = 2L * 10 * 131072, n1 = 2L * 16 * 131072;
    for (long i = (long)blockIdx.x * blockDim.x + threadIdx.x; i < n0 + n1;
         i += (long)gridDim.x * blockDim.x) {
        long j = i;
        const float* W = W0;
        uint2* dst = &g_w0[0][0][0][0][0];
        int nch = 10;
        if (j >= n0) { j -= n0; W = W1; dst = &g_w1[0][0][0][0][0]; nch = 16; }
        int c   = (int)(j & 63);
        int p   = (int)((j >> 6) & 31);
        int cb  = (int)((j >> 11) & 63);
        int rest = (int)(j >> 17);
        int kh  = rest / nch;
        int ch  = rest % nch;
        int gcol = ((c >> 4) & 3) * HH + cb * 16 + (c & 15);
        int P = kh * (nch * 32) + ch * 32 + p;
        int k0 = 2 * P;
        dst[(j & ~63L) | (long)(c ^ ((p & 3) << 2))] =
            pack_pair(W[(size_t)k0 * 4096 + gcol],
                      W[(size_t)(k0 + 1) * 4096 + gcol]);
    }
}

__global__ void __launch_bounds__(NTHR, 1)
lstm_main(const int* __restrict__ il,
          const float* __restrict__ b0g,
          const float* __restrict__ b1g,
          float* __restrict__ out) {
    extern __shared__ char smem[];
    float* Zs  = (float*)(smem + ZS_OFF);         // [128][72]
    float* sb0 = (float*)(smem + SB_OFF);         // 64 cols
    float* sb1 = (float*)(smem + SB_OFF + 256);
    const uint32_t sbase = s2u(smem);

    const int tid = threadIdx.x;
    const int wid = tid >> 5, lid = tid & 31;
    const int cta = blockIdx.x;
    const int kh  = cta & 1;          // K-half of this CTA
    const int c64 = cta >> 1;         // gate-column group (16 hidden units)
    const int g = lid >> 2, q = lid & 3;
    const int mt  = wid >> 2;         // m-tile (32 rows)
    const int kq  = (wid >> 1) & 1;   // K-quarter within chunk (16 pairs)
    const int nhh = wid & 1;          // N-half (32 cols)
    const int xr  = q << 2;           // fragment swizzle

    const unsigned baseA = *(volatile unsigned*)&g_genA;
    const unsigned baseB = *(volatile unsigned*)&g_genB;
    const unsigned basez = *(volatile unsigned*)&g_zcnt[c64];

    if (tid == 0) {
        for (int s = 0; s < NSTG; s++) {
            mbar_init(sbase + EMPTY_MB(s), 16);
            mbar_init(sbase + B_MB(s), 1);
            for (int mb = 0; mb < 4; mb++) mbar_init(sbase + A_MB(s, mb), 1);
        }
    }
    if (tid < 64) {
        int gc = ((tid >> 4) & 3) * HH + c64 * 16 + (tid & 15);
        sb0[tid] = b0g[gc];
        sb1[tid] = b1g[gc];
    }
    {
        uint2 z2 = make_uint2(0u, 0u);
        uint2* z0 = &g_h0[0][0][0][0];
        uint2* z1 = &g_h1[0][0][0][0];
        for (int i = cta * NTHR + tid; i < 4 * 512 * 32; i += NCTA * NTHR) { z0[i] = z2; z1[i] = z2; }
    }
    __syncthreads();

    if (tid == 0) arrive_evt(&g_cntB, &g_genB);
    wait_gen(&g_genB, baseB, 1u);

    if (wid == 16) {
        // ============ dedicated free-running producer (lanes 0..4) ============
        if (lid < 8) {
            int pstg = 0, pph = 1;
            for (int t = 0; t < TT; t++) {
                const int pr = t & 1, pw = pr ^ 1;
                const int nt  = __ldg(&g_nt[t]);
                if (nt == 0) continue;
                const int nmb = (nt + 31) >> 5;

                // ---- layer 0: 10 chunks of this CTA's K-half ----
                // kh=0: pairs 0..319  = x[0..127] + h0[0..191]
                // kh=1: pairs 320..639 = h0[192..511]
                for (int c = 0; c < 10; c++) {
                    if (t >= 1 && ((kh == 0 && c == 4) || (kh == 1 && c == 0)))
                        wait_gen(&g_genA, baseA, (unsigned)t);   // h0[pr] ready
                    mwait(sbase + EMPTY_MB(pstg), (unsigned)pph);
                    if (lid < nmb) {
                        const uint2* ap;
                        if (kh == 0)
                            ap = (c < 4) ? &g_x[t][lid][c * 32][0]
                                         : &g_h0[pr][lid][(c - 4) * 32][0];
                        else
                            ap = &g_h0[pr][lid][192 + c * 32][0];
                        mexpect(sbase + A_MB(pstg, lid), 8192u);
                        bulk(sbase + pstg * STAGE_SZ + lid * 8192, ap, 8192u,
                             sbase + A_MB(pstg, lid));
                    }
                    if (lid == 4) {
                        mexpect(sbase + B_MB(pstg), 16384u);
                        bulk(sbase + pstg * STAGE_SZ + 32768, &g_w0[kh][c][c64][0][0],
                             16384u, sbase + B_MB(pstg));
                    }
                    if (++pstg == NSTG) { pstg = 0; pph ^= 1; }
                }
                // ---- layer 1: 16 chunks ----
                // kh=0: h0[pw] (gate mid(t)) ; kh=1: h1[pr] (gate end(t-1))
                if (kh == 0) wait_gen(&g_genA, baseA, (unsigned)(t + 1));
                else         wait_gen(&g_genB, baseB, (unsigned)t);
                for (int c = 0; c < 16; c++) {
                    mwait(sbase + EMPTY_MB(pstg), (unsigned)pph);
                    if (lid < nmb) {
                        const uint2* ap = (kh == 0) ? &g_h0[pw][lid][c * 32][0]
                                                    : &g_h1[pr][lid][c * 32][0];
                        mexpect(sbase + A_MB(pstg, lid), 8192u);
                        bulk(sbase + pstg * STAGE_SZ + lid * 8192, ap, 8192u,
                             sbase + A_MB(pstg, lid));
                    }
                    if (lid == 4) {
                        mexpect(sbase + B_MB(pstg), 16384u);
                        bulk(sbase + pstg * STAGE_SZ + 32768, &g_w1[kh][c][c64][0][0],
                             16384u, sbase + B_MB(pstg));
                    }
                    if (++pstg == NSTG) { pstg = 0; pph ^= 1; }
                }
            }
        }
    } else {
        // ================= compute + exchange + cell (warps 0..15) =================
        const int lr = tid >> 2;                 // local row 0..63 (tid<256)
        const int mrow = kh * 64 + lr;           // owned sorted row
        const int u0 = (tid & 3) * 4;            // hidden units u0..u0+3
        float cs0[4] = {0.f, 0.f, 0.f, 0.f};
        float cs1[4] = {0.f, 0.f, 0.f, 0.f};
        const int om    = (tid < 256) ? g_perm[mrow] : 0;
        const int mylen = (tid < 256) ? g_plen[mrow] : 0;
        int cstg = 0, cph = 0;
        unsigned zk = 0;

        for (int t = 0; t < TT; t++) {
            const int pw = (t & 1) ^ 1;
            const int par = t & 1;
            const int nt = __ldg(&g_nt[t]);
            for (int layer = 0; layer < 2; layer++) {
                if (nt == 0) {
                    if (tid == 0) {
                        if (layer == 0) arrive_evt(&g_cntA, &g_genA);
                        else            arrive_evt(&g_cntB, &g_genB);
                    }
                    continue;
                }
                const int nc = layer ? 16 : 10;
                const int nmb = (nt + 31) >> 5;
                const bool live = (mt < nmb);

                float C[2][4][4];
#pragma unroll
                for (int a = 0; a < 2; a++)
#pragma unroll
                    for (int b = 0; b < 4; b++)
#pragma unroll
                        for (int d = 0; d < 4; d++) C[a][b][d] = 0.f;

                for (int ch = 0; ch < nc; ch++) {
                    mwait(sbase + B_MB(cstg), (unsigned)cph);
                    if (live) {
                        mwait(sbase + A_MB(cstg, mt), (unsigned)cph);
                        const uint2* Ab = (const uint2*)(smem + cstg * STAGE_SZ) + mt * 1024;
                        const uint2* Bb = (const uint2*)(smem + cstg * STAGE_SZ + 32768);
#pragma unroll
                        for (int sl = 0; sl < 2; sl++) {
                            const int pp = kq * 16 + sl * 8 + q;
                            const int pa = pp * 32;
                            const int pb = (pp + 4) * 32;
                            uint2 Af[2][4];
                            uint2 Bf[4][2];
#pragma unroll
                            for (int rt = 0; rt < 2; rt++) {
                                const int v0 = (rt * 16 + g) ^ xr;
                                const int v1 = (rt * 16 + g + 8) ^ xr;
                                Af[rt][0] = Ab[pa + v0];
                                Af[rt][1] = Ab[pa + v1];
                                Af[rt][2] = Ab[pb + v0];
                                Af[rt][3] = Ab[pb + v1];
                            }
                            const int ba  = pp * 64;
                            const int bb2 = (pp + 4) * 64;
#pragma unroll
                            for (int nt2 = 0; nt2 < 4; nt2++) {
                                const int cc = (nhh * 32 + nt2 * 8 + g) ^ xr;
                                Bf[nt2][0] = Bb[ba + cc];
                                Bf[nt2][1] = Bb[bb2 + cc];
                            }
#pragma unroll
                            for (int rt = 0; rt < 2; rt++)
#pragma unroll
                                for (int nt2 = 0; nt2 < 4; nt2++) {
                                    bmma(C[rt][nt2], Af[rt][0].x, Af[rt][1].x,
                                         Af[rt][2].x, Af[rt][3].x,
                                         Bf[nt2][0].x, Bf[nt2][1].x);
                                    bmma(C[rt][nt2], Af[rt][0].y, Af[rt][1].y,
                                         Af[rt][2].y, Af[rt][3].y,
                                         Bf[nt2][0].x, Bf[nt2][1].x);
                                    bmma(C[rt][nt2], Af[rt][0].x, Af[rt][1].x,
                                         Af[rt][2].x, Af[rt][3].x,
                                         Bf[nt2][0].y, Bf[nt2][1].y);
                                }
                        }
                    }
                    __syncwarp();
                    if (lid == 0) marrive(sbase + EMPTY_MB(cstg));
                    if (++cstg == NSTG) { cstg = 0; cph ^= 1; }
                }

                // reduce K-quarters: kq0 store, kq1 add
                const int R = mt * 32;
                if (live && kq == 0) {
#pragma unroll
                    for (int rt = 0; rt < 2; rt++)
#pragma unroll
                        for (int nt2 = 0; nt2 < 4; nt2++) {
                            const int col = nhh * 32 + nt2 * 8 + 2 * q;
                            *(float2*)&Zs[(R + rt * 16 + g) * 72 + col] =
                                make_float2(C[rt][nt2][0], C[rt][nt2][1]);
                            *(float2*)&Zs[(R + rt * 16 + g + 8) * 72 + col] =
                                make_float2(C[rt][nt2][2], C[rt][nt2][3]);
                        }
                }
                barc();
                if (live && kq == 1) {
#pragma unroll
                    for (int rt = 0; rt < 2; rt++)
#pragma unroll
                        for (int nt2 = 0; nt2 < 4; nt2++) {
                            const int col = nhh * 32 + nt2 * 8 + 2 * q;
                            float2 v0 = *(float2*)&Zs[(R + rt * 16 + g) * 72 + col];
                            float2 v1 = *(float2*)&Zs[(R + rt * 16 + g + 8) * 72 + col];
                            v0.x += C[rt][nt2][0]; v0.y += C[rt][nt2][1];
                            v1.x += C[rt][nt2][2]; v1.y += C[rt][nt2][3];
                            *(float2*)&Zs[(R + rt * 16 + g) * 72 + col] = v0;
                            *(float2*)&Zs[(R + rt * 16 + g + 8) * 72 + col] = v1;
                        }
                }
                barc();

                // ---- pair exchange: upload partner-rows partial, add partner's ----
                if (tid < 256) {
                    const int c0 = (tid & 3) * 16;
                    const float* zsrc = &Zs[((1 ^ kh) * 64 + lr) * 72 + c0];
                    float* zdst = &g_zx[par][layer][c64][(1 ^ kh) * 64 + lr][c0];
#pragma unroll
                    for (int k2 = 0; k2 < 4; k2++)
                        *(float4*)(zdst + k2 * 4) = *(const float4*)(zsrc + k2 * 4);
                    __threadfence();
                }
                barc();
                zk++;
                if (tid == 0) {
                    __threadfence();
                    atomicAdd(&g_zcnt[c64], 1u);
                    while ((*(volatile unsigned*)&g_zcnt[c64]) - basez < 2u * zk) {
                        __nanosleep(32);
                    }
                    __threadfence();
                }
                barc();
                if (tid < 256) {
                    const int c0 = (tid & 3) * 16;
                    const float* zr = &g_zx[par][layer][c64][mrow][c0];
                    float* zd = &Zs[mrow * 72 + c0];
#pragma unroll
                    for (int k2 = 0; k2 < 4; k2++) {
                        float4 a = *(const float4*)(zr + k2 * 4);
                        float4 b = *(float4*)(zd + k2 * 4);
                        b.x += a.x; b.y += a.y; b.z += a.z; b.w += a.w;
                        *(float4*)(zd + k2 * 4) = b;
                    }
                }
                barc();

                // cell: own rows only
                if (tid < 256 && mrow < nt) {
                    const float* sb = layer ? sb1 : sb0;
                    float* cs = layer ? cs1 : cs0;
                    const float* zrow = &Zs[mrow * 72];
                    float4 vi = *(float4*)&zrow[u0];
                    float4 vj = *(float4*)&zrow[16 + u0];
                    float4 vf = *(float4*)&zrow[32 + u0];
                    float4 vo = *(float4*)&zrow[48 + u0];
                    float ziv[4] = {vi.x, vi.y, vi.z, vi.w};
                    float zjv[4] = {vj.x, vj.y, vj.z, vj.w};
                    float zfv[4] = {vf.x, vf.y, vf.z, vf.w};
                    float zov[4] = {vo.x, vo.y, vo.z, vo.w};
                    float nh[4];
#pragma unroll
                    for (int j = 0; j < 4; j++) {
                        float zi = ziv[j] + sb[u0 + j];
                        float zj = zjv[j] + sb[16 + u0 + j];
                        float zf = zfv[j] + sb[32 + u0 + j];
                        float zo = zov[j] + sb[48 + u0 + j];
                        float nc2 = cs[j] * sigf(zf + 1.0f) + sigf(zi) * tanf_fast(zj);
                        nh[j] = tanf_fast(nc2) * sigf(zo);
                        cs[j] = nc2;
                    }
                    uint2 p0 = pack_pair(nh[0], nh[1]);
                    uint2 p1 = pack_pair(nh[2], nh[3]);
                    const int pg = c64 * 8 + (tid & 3) * 2;
                    const int mb = mrow >> 5;
                    const int m0 = (mrow & 31) ^ ((pg & 3) << 2);
                    const int m1 = (mrow & 31) ^ (((pg + 1) & 3) << 2);
                    if (layer == 0) {
                        g_h0[pw][mb][pg][m0] = p0;
                        g_h0[pw][mb][pg + 1][m1] = p1;
                    } else {
                        g_h1[pw][mb][pg][m0] = p0;
                        g_h1[pw][mb][pg + 1][m1] = p1;
                        if (t == mylen - 1)
                            *(float4*)&out[om * HH + c64 * 16 + u0] =
                                make_float4(nh[0], nh[1], nh[2], nh[3]);
                    }
                }
                barc();   // h writes done before tid0 arrives; protects Zs reuse

                if (tid == 0) {
                    if (layer == 0) arrive_evt(&g_cntA, &g_genA);  // mid(t)
                    else            arrive_evt(&g_cntB, &g_genB);  // end(t)
                }
            }
        }
    }
}

extern "C" void kernel_launch(void* const* d_in, const int* in_sizes, int n_in,
                              void* d_out, int out_size) {
    const int*   input_batch   = (const int*)d_in[0];
    const int*   input_lengths = (const int*)d_in[1];
    const float* emb           = (const float*)d_in[2];
    const float* W0            = (const float*)d_in[3];
    const float* b0            = (const float*)d_in[4];
    const float* W1            = (const float*)d_in[5];
    const float* b1            = (const float*)d_in[6];
    float*       out           = (float*)d_out;

    cudaFuncSetAttribute(lstm_main, cudaFuncAttributeMaxDynamicSharedMemorySize, SMEM_DYN);
    prep_perm<<<1, 128>>>(input_lengths);
    prep_x<<<1024, 256>>>(input_batch, emb);
    prep_w<<<2048, 256>>>(W0, W1);
    lstm_main<<<NCTA, NTHR, SMEM_DYN>>>(input_lengths, b0, b1, out);
}